// round 4
// baseline (speedup 1.0000x reference)
#include <cuda_runtime.h>
#include <cstdint>

// Problem constants
#define BSZ    4
#define NSEQ   1024
#define DMODEL 1024
#define NHEAD  16
#define DHEAD  64
#define FFDIM  4096
#define MROWS  (BSZ * NSEQ)   // 4096

// ---------------------------------------------------------------------------
// Scratch (device globals; no dynamic allocation allowed)
// ---------------------------------------------------------------------------
__device__ float g_h  [(size_t)MROWS * DMODEL];
__device__ float g_qkv[(size_t)MROWS * 3 * DMODEL];
__device__ float g_S  [4ULL * 16 * 1024 * 1024];        // 256 MB scores/probs
__device__ float g_o  [(size_t)MROWS * DMODEL];
__device__ float g_ff [(size_t)MROWS * FFDIM];
__device__ float g_wq [3 * DMODEL * DMODEL];            // tf32-rounded weights
__device__ float g_wo [DMODEL * DMODEL];
__device__ float g_wf1[(size_t)FFDIM * DMODEL];
__device__ float g_wf2[(size_t)FFDIM * DMODEL];

// ---------------------------------------------------------------------------
// Helpers
// ---------------------------------------------------------------------------
__device__ __forceinline__ float tf32r(float x) {
    unsigned u;
    asm("cvt.rna.tf32.f32 %0, %1;" : "=r"(u) : "f"(x));
    return __uint_as_float(u);
}

__device__ __forceinline__ void cpa16(float* s, const float* g) {
    unsigned sa = (unsigned)__cvta_generic_to_shared(s);
    asm volatile("cp.async.cg.shared.global [%0], [%1], 16;" :: "r"(sa), "l"(g));
}

__device__ __forceinline__ void mma8(float* c, const unsigned* a, const unsigned* b) {
    asm volatile(
        "mma.sync.aligned.m16n8k8.row.col.f32.tf32.tf32.f32 "
        "{%0,%1,%2,%3}, {%4,%5,%6,%7}, {%8,%9}, {%0,%1,%2,%3};"
        : "+f"(c[0]), "+f"(c[1]), "+f"(c[2]), "+f"(c[3])
        : "r"(a[0]), "r"(a[1]), "r"(a[2]), "r"(a[3]), "r"(b[0]), "r"(b[1]));
}

__device__ __forceinline__ float gelu_tanh(float x) {
    float x3 = x * x * x;
    float u = 0.7978845608028654f * (x + 0.044715f * x3);
    return 0.5f * x * (1.0f + tanhf(u));
}

// ---------------------------------------------------------------------------
// Weight prep: round to tf32 (rna)
// ---------------------------------------------------------------------------
__global__ void round_k(const float* __restrict__ src, float* __restrict__ dst, int n4)
{
    int i = blockIdx.x * blockDim.x + threadIdx.x;
    if (i < n4) {
        float4 v = ((const float4*)src)[i];
        v.x = tf32r(v.x); v.y = tf32r(v.y); v.z = tf32r(v.z); v.w = tf32r(v.w);
        ((float4*)dst)[i] = v;
    }
}

// ---------------------------------------------------------------------------
// LayerNorm (output feeds a GEMM A operand -> tf32-round the result)
// ---------------------------------------------------------------------------
__global__ void __launch_bounds__(256) ln_kernel(
    const float* __restrict__ x, const float* __restrict__ w,
    const float* __restrict__ b, float* __restrict__ out)
{
    int row = blockIdx.x;
    int t = threadIdx.x;
    const float4* xr = (const float4*)(x + (size_t)row * DMODEL);
    float4 v = xr[t];
    float s  = v.x + v.y + v.z + v.w;
    float ss = v.x*v.x + v.y*v.y + v.z*v.z + v.w*v.w;
    #pragma unroll
    for (int o = 16; o; o >>= 1) {
        s  += __shfl_xor_sync(0xffffffffu, s,  o);
        ss += __shfl_xor_sync(0xffffffffu, ss, o);
    }
    __shared__ float rs[8], rss[8];
    int wid = t >> 5, ln = t & 31;
    if (ln == 0) { rs[wid] = s; rss[wid] = ss; }
    __syncthreads();
    if (t < 32) {
        s  = (ln < 8) ? rs[ln]  : 0.f;
        ss = (ln < 8) ? rss[ln] : 0.f;
        #pragma unroll
        for (int o = 4; o; o >>= 1) {
            s  += __shfl_xor_sync(0xffffffffu, s,  o);
            ss += __shfl_xor_sync(0xffffffffu, ss, o);
        }
        if (ln == 0) { rs[0] = s; rss[0] = ss; }
    }
    __syncthreads();
    float mean = rs[0] * (1.0f / DMODEL);
    float var  = rss[0] * (1.0f / DMODEL) - mean * mean;
    float inv  = rsqrtf(var + 1e-5f);
    float4 wv = ((const float4*)w)[t];
    float4 bv = ((const float4*)b)[t];
    float4 o4;
    o4.x = tf32r((v.x - mean) * inv * wv.x + bv.x);
    o4.y = tf32r((v.y - mean) * inv * wv.y + bv.y);
    o4.z = tf32r((v.z - mean) * inv * wv.z + bv.z);
    o4.w = tf32r((v.w - mean) * inv * wv.w + bv.w);
    ((float4*)(out + (size_t)row * DMODEL))[t] = o4;
}

// ---------------------------------------------------------------------------
// Big dense GEMM: C = epi(A @ W^T + bias)   (tf32 mma.sync, 4-stage cp.async)
//   A [M,K] row-major, W [N,K] row-major. Tile 128x128x16, 256 threads,
//   warp tile 32x64 (MI=2, NI=8). One __syncthreads per k-tile (stage dist 3).
//   EPI: 0=+bias  2=gelu(+bias)  3=res+gamma*(+bias);  ROUND: tf32-round C.
// ---------------------------------------------------------------------------
template <int EPI, int ROUND>
__global__ void __launch_bounds__(256, 2) gemm_big(
    const float* __restrict__ A, const float* __restrict__ W,
    const float* __restrict__ bias, float* __restrict__ C,
    const float* __restrict__ res, const float* __restrict__ gamma,
    int K, int lda, int ldb, int ldc)
{
    constexpr int SA = 20;               // row stride (floats), conflict-free
    constexpr int STG = 128 * SA;        // floats per A (or B) stage

    extern __shared__ float sm[];
    float* As = sm;                      // [4][128][20]
    float* Bs = sm + 4 * STG;            // [4][128][20]

    int m0 = blockIdx.y * 128;
    int n0 = blockIdx.x * 128;

    int t = threadIdx.x;
    int lane = t & 31, wid = t >> 5;
    int g = lane >> 2, q4 = lane & 3;
    int wm0 = (wid & 3) * 32;
    int wn0 = (wid >> 2) * 64;

    float acc[2][8][4];
    #pragma unroll
    for (int mi = 0; mi < 2; mi++)
        #pragma unroll
        for (int ni = 0; ni < 8; ni++)
            #pragma unroll
            for (int r = 0; r < 4; r++) acc[mi][ni][r] = 0.f;

    const float* Abase = A + (size_t)m0 * lda;
    const float* Bbase = W + (size_t)n0 * ldb;

    int crow = t >> 2, cch = (t & 3) << 2;   // copy mapping: 128 rows x 16 k

    auto issue = [&](int s, int kt) {
        const float* Asrc = Abase + kt * 16 + cch;
        const float* Bsrc = Bbase + kt * 16 + cch;
        float* Ad = As + s * STG + cch;
        float* Bd = Bs + s * STG + cch;
        #pragma unroll
        for (int i = 0; i < 2; i++) {
            int row = crow + i * 64;
            cpa16(Ad + row * SA, Asrc + (size_t)row * lda);
            cpa16(Bd + row * SA, Bsrc + (size_t)row * ldb);
        }
        asm volatile("cp.async.commit_group;");
    };

    int KT = K / 16;
    issue(0, 0); issue(1, 1); issue(2, 2);

    for (int kt = 0; kt < KT; kt++) {
        asm volatile("cp.async.wait_group 2;");
        __syncthreads();
        if (kt + 3 < KT) issue((kt + 3) & 3, kt + 3);
        const float* Asg = As + (kt & 3) * STG;
        const float* Bsg = Bs + (kt & 3) * STG;
        #pragma unroll
        for (int ks = 0; ks < 2; ks++) {
            unsigned a[2][4];
            #pragma unroll
            for (int mi = 0; mi < 2; mi++) {
                const float* p = Asg + (wm0 + mi * 16 + g) * SA + ks * 8 + q4;
                a[mi][0] = __float_as_uint(p[0]);
                a[mi][1] = __float_as_uint(p[8 * SA]);
                a[mi][2] = __float_as_uint(p[4]);
                a[mi][3] = __float_as_uint(p[8 * SA + 4]);
            }
            unsigned b[8][2];
            #pragma unroll
            for (int ni = 0; ni < 8; ni++) {
                const float* p = Bsg + (wn0 + ni * 8 + g) * SA + ks * 8 + q4;
                b[ni][0] = __float_as_uint(p[0]);
                b[ni][1] = __float_as_uint(p[4]);
            }
            #pragma unroll
            for (int mi = 0; mi < 2; mi++)
                #pragma unroll
                for (int ni = 0; ni < 8; ni++)
                    mma8(acc[mi][ni], a[mi], b[ni]);
        }
    }

    // Epilogue
    #pragma unroll
    for (int mi = 0; mi < 2; mi++) {
        int r0 = m0 + wm0 + mi * 16 + g;
        #pragma unroll
        for (int ni = 0; ni < 8; ni++) {
            int cb = n0 + wn0 + ni * 8 + 2 * q4;
            float2 b2 = *(const float2*)(bias + cb);
            float* a4 = acc[mi][ni];
            float v0 = a4[0] + b2.x, v1 = a4[1] + b2.y;
            float v2 = a4[2] + b2.x, v3 = a4[3] + b2.y;
            if (EPI == 2) {
                v0 = gelu_tanh(v0); v1 = gelu_tanh(v1);
                v2 = gelu_tanh(v2); v3 = gelu_tanh(v3);
            }
            if (EPI == 3) {
                float2 g2 = *(const float2*)(gamma + cb);
                float2 rA = *(const float2*)(res + (size_t)r0 * ldc + cb);
                float2 rB = *(const float2*)(res + (size_t)(r0 + 8) * ldc + cb);
                v0 = rA.x + g2.x * v0; v1 = rA.y + g2.y * v1;
                v2 = rB.x + g2.x * v2; v3 = rB.y + g2.y * v3;
            }
            if (ROUND) {
                v0 = tf32r(v0); v1 = tf32r(v1); v2 = tf32r(v2); v3 = tf32r(v3);
            }
            *(float2*)(C + (size_t)r0 * ldc + cb)       = make_float2(v0, v1);
            *(float2*)(C + (size_t)(r0 + 8) * ldc + cb) = make_float2(v2, v3);
        }
    }
}

// ---------------------------------------------------------------------------
// mma.sync TF32 GEMM (QK^T and P@V; batched)
// ---------------------------------------------------------------------------
template <int BN, int TRANSB, int EPI, int ROUND>
__global__ void __launch_bounds__(256, 2) gemm_tc(
    const float* __restrict__ A, const float* __restrict__ Bm,
    const float* __restrict__ bias, float* __restrict__ C,
    const float* __restrict__ res, const float* __restrict__ gamma,
    int K, int lda, int ldb, int ldc,
    long long sAb, long long sAh, long long sBb, long long sBh,
    long long sCb, long long sCh, int Hdim, float scale)
{
    constexpr int BM = 128, BK = 32;
    constexpr int SA  = 36;
    constexpr int SBT = 36;
    constexpr int SBN = BN + 8;
    constexpr int ASTG = BM * SA;
    constexpr int BSTG = TRANSB ? BN * SBT : BK * SBN;
    constexpr int WN = BN / 2;
    constexpr int MI = 2, NI = WN / 8;

    extern __shared__ float smem_g[];
    float* As = smem_g;
    float* Bs = smem_g + 2 * ASTG;

    int bz = blockIdx.z;
    int bb = bz / Hdim, hh = bz - bb * Hdim;
    A  += (size_t)bb * sAb + (size_t)hh * sAh;
    Bm += (size_t)bb * sBb + (size_t)hh * sBh;
    C  += (size_t)bb * sCb + (size_t)hh * sCh;

    int m0 = blockIdx.y * BM;
    int n0 = blockIdx.x * BN;

    int t = threadIdx.x;
    int lane = t & 31, wid = t >> 5;
    int g = lane >> 2, q4 = lane & 3;
    int wm0 = (wid & 3) * 32;
    int wn0 = (wid >> 2) * WN;

    float acc[MI][NI][4];
    #pragma unroll
    for (int mi = 0; mi < MI; mi++)
        #pragma unroll
        for (int ni = 0; ni < NI; ni++)
            #pragma unroll
            for (int rr = 0; rr < 4; rr++) acc[mi][ni][rr] = 0.f;

    int ar = t >> 1, ak = (t & 1) * 8;
    int br = t >> 2, bk = (t & 3) * 4;
    int bkk = t >> 4, bnn = (t & 15) * 4;

    const float* Abase = A + (size_t)m0 * lda;
    const float* Bbase = TRANSB ? (Bm + (size_t)n0 * ldb) : (Bm + n0);

    int KT = K / BK;

    auto issue = [&](int stage, int kt) {
        float* Ad = As + stage * ASTG;
        const float* Asrc = Abase + kt * BK;
        #pragma unroll
        for (int i2 = 0; i2 < 4; i2++) {
            int c = i2 * 256 + t;
            int row = c >> 3, ch = (c & 7) << 2;
            cpa16(Ad + row * SA + ch, Asrc + (size_t)row * lda + ch);
        }
        float* Bd = Bs + stage * BSTG;
        if (TRANSB) {
            const float* Bsrc = Bbase + kt * BK;
            #pragma unroll
            for (int i2 = 0; i2 < BN / 32; i2++) {
                int c = i2 * 256 + t;
                int row = c >> 3, ch = (c & 7) << 2;
                cpa16(Bd + row * SBT + ch, Bsrc + (size_t)row * ldb + ch);
            }
        } else {
            const float* Bsrc = Bbase + (size_t)kt * BK * ldb;
            #pragma unroll
            for (int i2 = 0; i2 < (BK * BN) / 1024; i2++) {
                int c = i2 * 256 + t;
                int row = c >> 4, ch = (c & 15) << 2;
                cpa16(Bd + row * SBN + ch, Bsrc + (size_t)row * ldb + ch);
            }
        }
    };

    auto compute = [&](int stage) {
        const float* Asg = As + stage * ASTG;
        const float* Bsg = Bs + stage * BSTG;
        #pragma unroll
        for (int ks = 0; ks < 4; ks++) {
            unsigned a[MI][4];
            #pragma unroll
            for (int mi = 0; mi < MI; mi++) {
                const float* p = Asg + (wm0 + mi * 16 + g) * SA + ks * 8 + q4;
                a[mi][0] = __float_as_uint(p[0]);
                a[mi][1] = __float_as_uint(p[8 * SA]);
                a[mi][2] = __float_as_uint(p[4]);
                a[mi][3] = __float_as_uint(p[8 * SA + 4]);
            }
            unsigned b[NI][2];
            #pragma unroll
            for (int ni = 0; ni < NI; ni++) {
                if (TRANSB) {
                    const float* p = Bsg + (wn0 + ni * 8 + g) * SBT + ks * 8 + q4;
                    b[ni][0] = __float_as_uint(p[0]);
                    b[ni][1] = __float_as_uint(p[4]);
                } else {
                    const float* p = Bsg + (ks * 8 + q4) * SBN + wn0 + ni * 8 + g;
                    b[ni][0] = __float_as_uint(p[0]);
                    b[ni][1] = __float_as_uint(p[4 * SBN]);
                }
            }
            #pragma unroll
            for (int mi = 0; mi < MI; mi++)
                #pragma unroll
                for (int ni = 0; ni < NI; ni++)
                    mma8(acc[mi][ni], a[mi], b[ni]);
        }
    };

    issue(0, 0);
    asm volatile("cp.async.commit_group;");
    for (int kt = 0; kt < KT; kt++) {
        if (kt + 1 < KT) {
            issue((kt + 1) & 1, kt + 1);
            asm volatile("cp.async.commit_group;");
            asm volatile("cp.async.wait_group 1;");
        } else {
            asm volatile("cp.async.wait_group 0;");
        }
        __syncthreads();
        compute(kt & 1);
        __syncthreads();
    }

    #pragma unroll
    for (int mi = 0; mi < MI; mi++) {
        int r0 = m0 + wm0 + mi * 16 + g;
        #pragma unroll
        for (int ni = 0; ni < NI; ni++) {
            int cb = n0 + wn0 + ni * 8 + 2 * q4;
            float bx = 0.f, by = 0.f;
            if ((EPI == 0 || EPI == 2 || EPI == 3) && bias) {
                float2 b2 = *(const float2*)(bias + cb);
                bx = b2.x; by = b2.y;
            }
            float* a4 = acc[mi][ni];
            float v0 = a4[0] + bx, v1 = a4[1] + by;
            float v2 = a4[2] + bx, v3 = a4[3] + by;
            if (EPI == 1) { v0 *= scale; v1 *= scale; v2 *= scale; v3 *= scale; }
            if (EPI == 2) {
                v0 = gelu_tanh(v0); v1 = gelu_tanh(v1);
                v2 = gelu_tanh(v2); v3 = gelu_tanh(v3);
            }
            if (EPI == 3) {
                float2 g2 = *(const float2*)(gamma + cb);
                float2 rA = *(const float2*)(res + (size_t)r0 * ldc + cb);
                float2 rB = *(const float2*)(res + (size_t)(r0 + 8) * ldc + cb);
                v0 = rA.x + g2.x * v0; v1 = rA.y + g2.y * v1;
                v2 = rB.x + g2.x * v2; v3 = rB.y + g2.y * v3;
            }
            if (ROUND) {
                v0 = tf32r(v0); v1 = tf32r(v1); v2 = tf32r(v2); v3 = tf32r(v3);
            }
            *(float2*)(C + (size_t)r0 * ldc + cb)       = make_float2(v0, v1);
            *(float2*)(C + (size_t)(r0 + 8) * ldc + cb) = make_float2(v2, v3);
        }
    }
}

// ---------------------------------------------------------------------------
// Fused talking-heads: mix -> softmax -> mix, in place on S.
// Single 64 KB smem buffer (in-place per-column mixes) -> 3 CTAs/SM.
// ---------------------------------------------------------------------------
__global__ void __launch_bounds__(512) attn_mix_softmax(
    const float* __restrict__ wl, const float* __restrict__ bl,
    const float* __restrict__ ww, const float* __restrict__ bw,
    float* __restrict__ S)
{
    extern __shared__ float Ssh[];      // [16][1024]
    __shared__ float wls[256], wws[256], bls[16], bws[16];

    int t = threadIdx.x;
    int b = blockIdx.x >> 10;
    int i = blockIdx.x & 1023;

    if (t < 256) { wls[t] = wl[t]; wws[t] = ww[t]; }
    if (t < 16)  { bls[t] = bl[t]; bws[t] = bw[t]; }

    float* Sg = S + (size_t)(b * NHEAD) * NSEQ * NSEQ + (size_t)i * NSEQ;

    #pragma unroll
    for (int ii = 0; ii < 8; ii++) {
        int idx4 = ii * 512 + t;
        int h = idx4 >> 8, j4 = idx4 & 255;
        ((float4*)(Ssh + h * NSEQ))[j4] =
            ((const float4*)(Sg + (size_t)h * NSEQ * NSEQ))[j4];
    }
    __syncthreads();

    // Pre-softmax mixing (in place: each thread owns its columns)
    #pragma unroll
    for (int jj = 0; jj < 2; jj++) {
        int j = t + jj * 512;
        float sv[16];
        #pragma unroll
        for (int h = 0; h < 16; h++) sv[h] = Ssh[h * NSEQ + j];
        #pragma unroll
        for (int gg = 0; gg < 16; gg++) {
            float acc = bls[gg];
            #pragma unroll
            for (int h = 0; h < 16; h++) acc += wls[gg * 16 + h] * sv[h];
            Ssh[gg * NSEQ + j] = acc;
        }
    }
    __syncthreads();

    // Softmax: one warp per head-row
    {
        int w = t >> 5, l = t & 31;
        float* row = Ssh + w * NSEQ;
        float mx = -1e30f;
        for (int m = l; m < NSEQ; m += 32) mx = fmaxf(mx, row[m]);
        #pragma unroll
        for (int o = 16; o; o >>= 1) mx = fmaxf(mx, __shfl_xor_sync(0xffffffffu, mx, o));
        float sum = 0.f;
        for (int m = l; m < NSEQ; m += 32) {
            float e = __expf(row[m] - mx);
            row[m] = e;
            sum += e;
        }
        #pragma unroll
        for (int o = 16; o; o >>= 1) sum += __shfl_xor_sync(0xffffffffu, sum, o);
        float inv = 1.f / sum;
        for (int m = l; m < NSEQ; m += 32) row[m] *= inv;
    }
    __syncthreads();

    // Post-softmax mixing (in place; tf32-round for the P@V GEMM)
    #pragma unroll
    for (int jj = 0; jj < 2; jj++) {
        int j = t + jj * 512;
        float pv[16];
        #pragma unroll
        for (int h = 0; h < 16; h++) pv[h] = Ssh[h * NSEQ + j];
        #pragma unroll
        for (int gg = 0; gg < 16; gg++) {
            float acc = bws[gg];
            #pragma unroll
            for (int h = 0; h < 16; h++) acc += wws[gg * 16 + h] * pv[h];
            Ssh[gg * NSEQ + j] = tf32r(acc);
        }
    }
    __syncthreads();

    #pragma unroll
    for (int ii = 0; ii < 8; ii++) {
        int idx4 = ii * 512 + t;
        int h = idx4 >> 8, j4 = idx4 & 255;
        ((float4*)(Sg + (size_t)h * NSEQ * NSEQ))[j4] =
            ((const float4*)(Ssh + h * NSEQ))[j4];
    }
}

// ---------------------------------------------------------------------------
// Launch
// ---------------------------------------------------------------------------
extern "C" void kernel_launch(void* const* d_in, const int* in_sizes, int n_in,
                              void* d_out, int out_size)
{
    const float* x      = (const float*)d_in[0];
    const float* ln1_w  = (const float*)d_in[1];
    const float* ln1_b  = (const float*)d_in[2];
    const float* qkv_w  = (const float*)d_in[3];
    const float* qkv_b  = (const float*)d_in[4];
    const float* pl_w   = (const float*)d_in[5];
    const float* pl_b   = (const float*)d_in[6];
    const float* pw_w   = (const float*)d_in[7];
    const float* pw_b   = (const float*)d_in[8];
    const float* out_w  = (const float*)d_in[9];
    const float* out_b  = (const float*)d_in[10];
    const float* gamma1 = (const float*)d_in[11];
    const float* ln2_w  = (const float*)d_in[12];
    const float* ln2_b  = (const float*)d_in[13];
    const float* fc1_w  = (const float*)d_in[14];
    const float* fc1_b  = (const float*)d_in[15];
    const float* fc2_w  = (const float*)d_in[16];
    const float* fc2_b  = (const float*)d_in[17];
    const float* gamma2 = (const float*)d_in[18];
    float* out = (float*)d_out;

    float *hbuf, *qkvp, *S, *obuf, *ff, *wq, *wo, *wf1, *wf2;
    cudaGetSymbolAddress((void**)&hbuf, g_h);
    cudaGetSymbolAddress((void**)&qkvp, g_qkv);
    cudaGetSymbolAddress((void**)&S,    g_S);
    cudaGetSymbolAddress((void**)&obuf, g_o);
    cudaGetSymbolAddress((void**)&ff,   g_ff);
    cudaGetSymbolAddress((void**)&wq,   g_wq);
    cudaGetSymbolAddress((void**)&wo,   g_wo);
    cudaGetSymbolAddress((void**)&wf1,  g_wf1);
    cudaGetSymbolAddress((void**)&wf2,  g_wf2);

    const int BIG_SMEM = 4 * 128 * 20 * 2 * 4;   // 81920 B

    cudaFuncSetAttribute(attn_mix_softmax,
                         cudaFuncAttributeMaxDynamicSharedMemorySize, 65536);
    cudaFuncSetAttribute(gemm_big<0,1>, cudaFuncAttributeMaxDynamicSharedMemorySize, BIG_SMEM);
    cudaFuncSetAttribute(gemm_big<2,1>, cudaFuncAttributeMaxDynamicSharedMemorySize, BIG_SMEM);
    cudaFuncSetAttribute(gemm_big<3,0>, cudaFuncAttributeMaxDynamicSharedMemorySize, BIG_SMEM);
    cudaFuncSetAttribute(gemm_tc<128,1,1,0>, cudaFuncAttributeMaxDynamicSharedMemorySize, 73728);
    cudaFuncSetAttribute(gemm_tc<64,0,0,1>,  cudaFuncAttributeMaxDynamicSharedMemorySize, 55296);

    const long long NN  = (long long)NSEQ * NSEQ;
    const long long SQK = (long long)NSEQ * 3 * DMODEL;

    // 0) Round weights to tf32
    round_k<<<3072, 256>>>(qkv_w, wq,  3 * DMODEL * DMODEL / 4);
    round_k<<<1024, 256>>>(out_w, wo,  DMODEL * DMODEL / 4);
    round_k<<<4096, 256>>>(fc1_w, wf1, FFDIM * DMODEL / 4);
    round_k<<<4096, 256>>>(fc2_w, wf2, FFDIM * DMODEL / 4);

    // 1) LN1
    ln_kernel<<<MROWS, 256>>>(x, ln1_w, ln1_b, hbuf);

    // 2) qkv = hbuf @ qkv_w^T + qkv_b
    gemm_big<0,1><<<dim3(24, 32), 256, BIG_SMEM>>>(
        hbuf, wq, qkv_b, qkvp, nullptr, nullptr,
        DMODEL, DMODEL, DMODEL, 3 * DMODEL);

    // 3) S[b,h] = (Q K^T) / 8
    gemm_tc<128,1,1,0><<<dim3(8, 8, 64), 256, 73728>>>(
        qkvp, qkvp + DMODEL, nullptr, S, nullptr, nullptr,
        DHEAD, 3 * DMODEL, 3 * DMODEL, NSEQ,
        SQK, DHEAD, SQK, DHEAD, (long long)NHEAD * NN, NN, NHEAD, 0.125f);

    // 4) talking-heads mix -> softmax -> mix
    attn_mix_softmax<<<BSZ * NSEQ, 512, 65536>>>(pl_w, pl_b, pw_w, pw_b, S);

    // 5) O[b,h] = P2 @ V
    gemm_tc<64,0,0,1><<<dim3(1, 8, 64), 256, 55296>>>(
        S, qkvp + 2 * DMODEL, nullptr, obuf, nullptr, nullptr,
        NSEQ, NSEQ, 3 * DMODEL, DMODEL,
        (long long)NHEAD * NN, NN, SQK, DHEAD,
        (long long)NSEQ * DMODEL, DHEAD, NHEAD, 1.f);

    // 6) x1 = x + gamma1 * (obuf @ out_w^T + out_b)
    gemm_big<3,0><<<dim3(8, 32), 256, BIG_SMEM>>>(
        obuf, wo, out_b, out, x, gamma1,
        DMODEL, DMODEL, DMODEL, DMODEL);

    // 7) LN2
    ln_kernel<<<MROWS, 256>>>(out, ln2_w, ln2_b, hbuf);

    // 8) ff = gelu(hbuf @ fc1_w^T + fc1_b)
    gemm_big<2,1><<<dim3(32, 32), 256, BIG_SMEM>>>(
        hbuf, wf1, fc1_b, ff, nullptr, nullptr,
        DMODEL, DMODEL, DMODEL, FFDIM);

    // 9) out = x1 + gamma2 * (ff @ fc2_w^T + fc2_b)
    gemm_big<3,0><<<dim3(8, 32), 256, BIG_SMEM>>>(
        ff, wf2, fc2_b, out, out, gamma2,
        FFDIM, FFDIM, FFDIM, DMODEL);
}

// round 5
// speedup vs baseline: 1.1148x; 1.1148x over previous
#include <cuda_runtime.h>
#include <cstdint>

// Problem constants
#define BSZ    4
#define NSEQ   1024
#define DMODEL 1024
#define NHEAD  16
#define DHEAD  64
#define FFDIM  4096
#define MROWS  (BSZ * NSEQ)   // 4096

// ---------------------------------------------------------------------------
// Scratch (device globals; no dynamic allocation allowed)
// ---------------------------------------------------------------------------
__device__ float g_h  [(size_t)MROWS * DMODEL];
__device__ float g_qkv[(size_t)MROWS * 3 * DMODEL];
__device__ float g_S  [4ULL * 16 * 1024 * 1024];        // 256 MB scores/probs
__device__ float g_o  [(size_t)MROWS * DMODEL];
__device__ float g_ff [(size_t)MROWS * FFDIM];
__device__ float g_wq [3 * DMODEL * DMODEL];            // tf32-rounded weights
__device__ float g_wo [DMODEL * DMODEL];
__device__ float g_wf1[(size_t)FFDIM * DMODEL];
__device__ float g_wf2[(size_t)FFDIM * DMODEL];

// ---------------------------------------------------------------------------
// Helpers
// ---------------------------------------------------------------------------
__device__ __forceinline__ float tf32r(float x) {
    unsigned u;
    asm("cvt.rna.tf32.f32 %0, %1;" : "=r"(u) : "f"(x));
    return __uint_as_float(u);
}

__device__ __forceinline__ void cpa16(float* s, const float* g) {
    unsigned sa = (unsigned)__cvta_generic_to_shared(s);
    asm volatile("cp.async.cg.shared.global [%0], [%1], 16;" :: "r"(sa), "l"(g));
}

__device__ __forceinline__ void mma8(float* c, const unsigned* a, const unsigned* b) {
    asm volatile(
        "mma.sync.aligned.m16n8k8.row.col.f32.tf32.tf32.f32 "
        "{%0,%1,%2,%3}, {%4,%5,%6,%7}, {%8,%9}, {%0,%1,%2,%3};"
        : "+f"(c[0]), "+f"(c[1]), "+f"(c[2]), "+f"(c[3])
        : "r"(a[0]), "r"(a[1]), "r"(a[2]), "r"(a[3]), "r"(b[0]), "r"(b[1]));
}

__device__ __forceinline__ float gelu_tanh(float x) {
    float x3 = x * x * x;
    float u = 0.7978845608028654f * (x + 0.044715f * x3);
    return 0.5f * x * (1.0f + tanhf(u));
}

// ---------------------------------------------------------------------------
// Weight prep: round to tf32 (rna)
// ---------------------------------------------------------------------------
__global__ void round_k(const float* __restrict__ src, float* __restrict__ dst, int n4)
{
    int i = blockIdx.x * blockDim.x + threadIdx.x;
    if (i < n4) {
        float4 v = ((const float4*)src)[i];
        v.x = tf32r(v.x); v.y = tf32r(v.y); v.z = tf32r(v.z); v.w = tf32r(v.w);
        ((float4*)dst)[i] = v;
    }
}

// ---------------------------------------------------------------------------
// LayerNorm (output feeds a GEMM A operand -> tf32-round the result)
// ---------------------------------------------------------------------------
__global__ void __launch_bounds__(256) ln_kernel(
    const float* __restrict__ x, const float* __restrict__ w,
    const float* __restrict__ b, float* __restrict__ out)
{
    int row = blockIdx.x;
    int t = threadIdx.x;
    const float4* xr = (const float4*)(x + (size_t)row * DMODEL);
    float4 v = xr[t];
    float s  = v.x + v.y + v.z + v.w;
    float ss = v.x*v.x + v.y*v.y + v.z*v.z + v.w*v.w;
    #pragma unroll
    for (int o = 16; o; o >>= 1) {
        s  += __shfl_xor_sync(0xffffffffu, s,  o);
        ss += __shfl_xor_sync(0xffffffffu, ss, o);
    }
    __shared__ float rs[8], rss[8];
    int wid = t >> 5, ln = t & 31;
    if (ln == 0) { rs[wid] = s; rss[wid] = ss; }
    __syncthreads();
    if (t < 32) {
        s  = (ln < 8) ? rs[ln]  : 0.f;
        ss = (ln < 8) ? rss[ln] : 0.f;
        #pragma unroll
        for (int o = 4; o; o >>= 1) {
            s  += __shfl_xor_sync(0xffffffffu, s,  o);
            ss += __shfl_xor_sync(0xffffffffu, ss, o);
        }
        if (ln == 0) { rs[0] = s; rss[0] = ss; }
    }
    __syncthreads();
    float mean = rs[0] * (1.0f / DMODEL);
    float var  = rss[0] * (1.0f / DMODEL) - mean * mean;
    float inv  = rsqrtf(var + 1e-5f);
    float4 wv = ((const float4*)w)[t];
    float4 bv = ((const float4*)b)[t];
    float4 o4;
    o4.x = tf32r((v.x - mean) * inv * wv.x + bv.x);
    o4.y = tf32r((v.y - mean) * inv * wv.y + bv.y);
    o4.z = tf32r((v.z - mean) * inv * wv.z + bv.z);
    o4.w = tf32r((v.w - mean) * inv * wv.w + bv.w);
    ((float4*)(out + (size_t)row * DMODEL))[t] = o4;
}

// ---------------------------------------------------------------------------
// TF32 tensor-core GEMM (round-2 proven config).
//   Block tile BM=128 x BN x BK=32, 256 threads (8 warps), warp tile 32 x BN/2.
//   mma.sync m16n8k8 tf32, cp.async double-buffered smem.
//   TRANSB=1: B is [N,K] row-major (C = A @ B^T);  TRANSB=0: B is [K,N].
//   EPI: 0=+bias  1=*scale  2=gelu(+bias)  3=res+gamma*(+bias)
//   ROUND: tf32-round C (when C feeds another GEMM as an operand)
// ---------------------------------------------------------------------------
template <int BN, int TRANSB, int EPI, int ROUND>
__global__ void __launch_bounds__(256, 2) gemm_tc(
    const float* __restrict__ A, const float* __restrict__ Bm,
    const float* __restrict__ bias, float* __restrict__ C,
    const float* __restrict__ res, const float* __restrict__ gamma,
    int K, int lda, int ldb, int ldc,
    long long sAb, long long sAh, long long sBb, long long sBh,
    long long sCb, long long sCh, int Hdim, float scale)
{
    constexpr int BM = 128, BK = 32;
    constexpr int SA  = 36;
    constexpr int SBT = 36;
    constexpr int SBN = BN + 8;
    constexpr int ASTG = BM * SA;
    constexpr int BSTG = TRANSB ? BN * SBT : BK * SBN;
    constexpr int WN = BN / 2;
    constexpr int MI = 2, NI = WN / 8;

    extern __shared__ float smem_g[];
    float* As = smem_g;
    float* Bs = smem_g + 2 * ASTG;

    int bz = blockIdx.z;
    int bb = bz / Hdim, hh = bz - bb * Hdim;
    A  += (size_t)bb * sAb + (size_t)hh * sAh;
    Bm += (size_t)bb * sBb + (size_t)hh * sBh;
    C  += (size_t)bb * sCb + (size_t)hh * sCh;

    int m0 = blockIdx.y * BM;
    int n0 = blockIdx.x * BN;

    int t = threadIdx.x;
    int lane = t & 31, wid = t >> 5;
    int g = lane >> 2, q4 = lane & 3;
    int wm0 = (wid & 3) * 32;
    int wn0 = (wid >> 2) * WN;

    float acc[MI][NI][4];
    #pragma unroll
    for (int mi = 0; mi < MI; mi++)
        #pragma unroll
        for (int ni = 0; ni < NI; ni++)
            #pragma unroll
            for (int rr = 0; rr < 4; rr++) acc[mi][ni][rr] = 0.f;

    const float* Abase = A + (size_t)m0 * lda;
    const float* Bbase = TRANSB ? (Bm + (size_t)n0 * ldb) : (Bm + n0);

    int KT = K / BK;

    auto issue = [&](int stage, int kt) {
        float* Ad = As + stage * ASTG;
        const float* Asrc = Abase + kt * BK;
        #pragma unroll
        for (int i2 = 0; i2 < 4; i2++) {
            int c = i2 * 256 + t;
            int row = c >> 3, ch = (c & 7) << 2;
            cpa16(Ad + row * SA + ch, Asrc + (size_t)row * lda + ch);
        }
        float* Bd = Bs + stage * BSTG;
        if (TRANSB) {
            const float* Bsrc = Bbase + kt * BK;
            #pragma unroll
            for (int i2 = 0; i2 < BN / 32; i2++) {
                int c = i2 * 256 + t;
                int row = c >> 3, ch = (c & 7) << 2;
                cpa16(Bd + row * SBT + ch, Bsrc + (size_t)row * ldb + ch);
            }
        } else {
            const float* Bsrc = Bbase + (size_t)kt * BK * ldb;
            #pragma unroll
            for (int i2 = 0; i2 < (BK * BN) / 1024; i2++) {
                int c = i2 * 256 + t;
                int row = c >> 4, ch = (c & 15) << 2;
                cpa16(Bd + row * SBN + ch, Bsrc + (size_t)row * ldb + ch);
            }
        }
    };

    auto compute = [&](int stage) {
        const float* Asg = As + stage * ASTG;
        const float* Bsg = Bs + stage * BSTG;
        #pragma unroll
        for (int ks = 0; ks < 4; ks++) {
            unsigned a[MI][4];
            #pragma unroll
            for (int mi = 0; mi < MI; mi++) {
                const float* p = Asg + (wm0 + mi * 16 + g) * SA + ks * 8 + q4;
                a[mi][0] = __float_as_uint(p[0]);
                a[mi][1] = __float_as_uint(p[8 * SA]);
                a[mi][2] = __float_as_uint(p[4]);
                a[mi][3] = __float_as_uint(p[8 * SA + 4]);
            }
            unsigned b[NI][2];
            #pragma unroll
            for (int ni = 0; ni < NI; ni++) {
                if (TRANSB) {
                    const float* p = Bsg + (wn0 + ni * 8 + g) * SBT + ks * 8 + q4;
                    b[ni][0] = __float_as_uint(p[0]);
                    b[ni][1] = __float_as_uint(p[4]);
                } else {
                    const float* p = Bsg + (ks * 8 + q4) * SBN + wn0 + ni * 8 + g;
                    b[ni][0] = __float_as_uint(p[0]);
                    b[ni][1] = __float_as_uint(p[4 * SBN]);
                }
            }
            #pragma unroll
            for (int mi = 0; mi < MI; mi++)
                #pragma unroll
                for (int ni = 0; ni < NI; ni++)
                    mma8(acc[mi][ni], a[mi], b[ni]);
        }
    };

    issue(0, 0);
    asm volatile("cp.async.commit_group;");
    for (int kt = 0; kt < KT; kt++) {
        if (kt + 1 < KT) {
            issue((kt + 1) & 1, kt + 1);
            asm volatile("cp.async.commit_group;");
            asm volatile("cp.async.wait_group 1;");
        } else {
            asm volatile("cp.async.wait_group 0;");
        }
        __syncthreads();
        compute(kt & 1);
        __syncthreads();
    }

    #pragma unroll
    for (int mi = 0; mi < MI; mi++) {
        int r0 = m0 + wm0 + mi * 16 + g;
        #pragma unroll
        for (int ni = 0; ni < NI; ni++) {
            int cb = n0 + wn0 + ni * 8 + 2 * q4;
            float bx = 0.f, by = 0.f;
            if ((EPI == 0 || EPI == 2 || EPI == 3) && bias) {
                float2 b2 = *(const float2*)(bias + cb);
                bx = b2.x; by = b2.y;
            }
            float* a4 = acc[mi][ni];
            float v0 = a4[0] + bx, v1 = a4[1] + by;
            float v2 = a4[2] + bx, v3 = a4[3] + by;
            if (EPI == 1) { v0 *= scale; v1 *= scale; v2 *= scale; v3 *= scale; }
            if (EPI == 2) {
                v0 = gelu_tanh(v0); v1 = gelu_tanh(v1);
                v2 = gelu_tanh(v2); v3 = gelu_tanh(v3);
            }
            if (EPI == 3) {
                float2 g2 = *(const float2*)(gamma + cb);
                float2 rA = *(const float2*)(res + (size_t)r0 * ldc + cb);
                float2 rB = *(const float2*)(res + (size_t)(r0 + 8) * ldc + cb);
                v0 = rA.x + g2.x * v0; v1 = rA.y + g2.y * v1;
                v2 = rB.x + g2.x * v2; v3 = rB.y + g2.y * v3;
            }
            if (ROUND) {
                v0 = tf32r(v0); v1 = tf32r(v1); v2 = tf32r(v2); v3 = tf32r(v3);
            }
            *(float2*)(C + (size_t)r0 * ldc + cb)       = make_float2(v0, v1);
            *(float2*)(C + (size_t)(r0 + 8) * ldc + cb) = make_float2(v2, v3);
        }
    }
}

// ---------------------------------------------------------------------------
// Fused talking-heads: mix -> softmax -> mix, in place on S.
// Single 64 KB smem buffer (in-place per-column mixes) -> 3 CTAs/SM.
// ---------------------------------------------------------------------------
__global__ void __launch_bounds__(512) attn_mix_softmax(
    const float* __restrict__ wl, const float* __restrict__ bl,
    const float* __restrict__ ww, const float* __restrict__ bw,
    float* __restrict__ S)
{
    extern __shared__ float Ssh[];      // [16][1024]
    __shared__ float wls[256], wws[256], bls[16], bws[16];

    int t = threadIdx.x;
    int b = blockIdx.x >> 10;
    int i = blockIdx.x & 1023;

    if (t < 256) { wls[t] = wl[t]; wws[t] = ww[t]; }
    if (t < 16)  { bls[t] = bl[t]; bws[t] = bw[t]; }

    float* Sg = S + (size_t)(b * NHEAD) * NSEQ * NSEQ + (size_t)i * NSEQ;

    #pragma unroll
    for (int ii = 0; ii < 8; ii++) {
        int idx4 = ii * 512 + t;
        int h = idx4 >> 8, j4 = idx4 & 255;
        ((float4*)(Ssh + h * NSEQ))[j4] =
            ((const float4*)(Sg + (size_t)h * NSEQ * NSEQ))[j4];
    }
    __syncthreads();

    // Pre-softmax mixing (in place: each thread owns its columns)
    #pragma unroll
    for (int jj = 0; jj < 2; jj++) {
        int j = t + jj * 512;
        float sv[16];
        #pragma unroll
        for (int h = 0; h < 16; h++) sv[h] = Ssh[h * NSEQ + j];
        #pragma unroll
        for (int gg = 0; gg < 16; gg++) {
            float acc = bls[gg];
            #pragma unroll
            for (int h = 0; h < 16; h++) acc += wls[gg * 16 + h] * sv[h];
            Ssh[gg * NSEQ + j] = acc;
        }
    }
    __syncthreads();

    // Softmax: one warp per head-row
    {
        int w = t >> 5, l = t & 31;
        float* row = Ssh + w * NSEQ;
        float mx = -1e30f;
        for (int m = l; m < NSEQ; m += 32) mx = fmaxf(mx, row[m]);
        #pragma unroll
        for (int o = 16; o; o >>= 1) mx = fmaxf(mx, __shfl_xor_sync(0xffffffffu, mx, o));
        float sum = 0.f;
        for (int m = l; m < NSEQ; m += 32) {
            float e = __expf(row[m] - mx);
            row[m] = e;
            sum += e;
        }
        #pragma unroll
        for (int o = 16; o; o >>= 1) sum += __shfl_xor_sync(0xffffffffu, sum, o);
        float inv = 1.f / sum;
        for (int m = l; m < NSEQ; m += 32) row[m] *= inv;
    }
    __syncthreads();

    // Post-softmax mixing (in place; tf32-round for the P@V GEMM)
    #pragma unroll
    for (int jj = 0; jj < 2; jj++) {
        int j = t + jj * 512;
        float pv[16];
        #pragma unroll
        for (int h = 0; h < 16; h++) pv[h] = Ssh[h * NSEQ + j];
        #pragma unroll
        for (int gg = 0; gg < 16; gg++) {
            float acc = bws[gg];
            #pragma unroll
            for (int h = 0; h < 16; h++) acc += wws[gg * 16 + h] * pv[h];
            Ssh[gg * NSEQ + j] = tf32r(acc);
        }
    }
    __syncthreads();

    #pragma unroll
    for (int ii = 0; ii < 8; ii++) {
        int idx4 = ii * 512 + t;
        int h = idx4 >> 8, j4 = idx4 & 255;
        ((float4*)(Sg + (size_t)h * NSEQ * NSEQ))[j4] =
            ((const float4*)(Ssh + h * NSEQ))[j4];
    }
}

// ---------------------------------------------------------------------------
// Launch
// ---------------------------------------------------------------------------
extern "C" void kernel_launch(void* const* d_in, const int* in_sizes, int n_in,
                              void* d_out, int out_size)
{
    const float* x      = (const float*)d_in[0];
    const float* ln1_w  = (const float*)d_in[1];
    const float* ln1_b  = (const float*)d_in[2];
    const float* qkv_w  = (const float*)d_in[3];
    const float* qkv_b  = (const float*)d_in[4];
    const float* pl_w   = (const float*)d_in[5];
    const float* pl_b   = (const float*)d_in[6];
    const float* pw_w   = (const float*)d_in[7];
    const float* pw_b   = (const float*)d_in[8];
    const float* out_w  = (const float*)d_in[9];
    const float* out_b  = (const float*)d_in[10];
    const float* gamma1 = (const float*)d_in[11];
    const float* ln2_w  = (const float*)d_in[12];
    const float* ln2_b  = (const float*)d_in[13];
    const float* fc1_w  = (const float*)d_in[14];
    const float* fc1_b  = (const float*)d_in[15];
    const float* fc2_w  = (const float*)d_in[16];
    const float* fc2_b  = (const float*)d_in[17];
    const float* gamma2 = (const float*)d_in[18];
    float* out = (float*)d_out;

    float *hbuf, *qkvp, *S, *obuf, *ff, *wq, *wo, *wf1, *wf2;
    cudaGetSymbolAddress((void**)&hbuf, g_h);
    cudaGetSymbolAddress((void**)&qkvp, g_qkv);
    cudaGetSymbolAddress((void**)&S,    g_S);
    cudaGetSymbolAddress((void**)&obuf, g_o);
    cudaGetSymbolAddress((void**)&ff,   g_ff);
    cudaGetSymbolAddress((void**)&wq,   g_wq);
    cudaGetSymbolAddress((void**)&wo,   g_wo);
    cudaGetSymbolAddress((void**)&wf1,  g_wf1);
    cudaGetSymbolAddress((void**)&wf2,  g_wf2);

    cudaFuncSetAttribute(attn_mix_softmax,
                         cudaFuncAttributeMaxDynamicSharedMemorySize, 65536);
    cudaFuncSetAttribute(gemm_tc<128,1,0,1>, cudaFuncAttributeMaxDynamicSharedMemorySize, 73728);
    cudaFuncSetAttribute(gemm_tc<128,1,1,0>, cudaFuncAttributeMaxDynamicSharedMemorySize, 73728);
    cudaFuncSetAttribute(gemm_tc<128,1,2,1>, cudaFuncAttributeMaxDynamicSharedMemorySize, 73728);
    cudaFuncSetAttribute(gemm_tc<128,1,3,0>, cudaFuncAttributeMaxDynamicSharedMemorySize, 73728);
    cudaFuncSetAttribute(gemm_tc<64,0,0,1>,  cudaFuncAttributeMaxDynamicSharedMemorySize, 55296);

    const long long NN  = (long long)NSEQ * NSEQ;
    const long long SQK = (long long)NSEQ * 3 * DMODEL;

    // 0) Round weights to tf32
    round_k<<<3072, 256>>>(qkv_w, wq,  3 * DMODEL * DMODEL / 4);
    round_k<<<1024, 256>>>(out_w, wo,  DMODEL * DMODEL / 4);
    round_k<<<4096, 256>>>(fc1_w, wf1, FFDIM * DMODEL / 4);
    round_k<<<4096, 256>>>(fc2_w, wf2, FFDIM * DMODEL / 4);

    // 1) LN1
    ln_kernel<<<MROWS, 256>>>(x, ln1_w, ln1_b, hbuf);

    // 2) qkv = hbuf @ qkv_w^T + qkv_b
    gemm_tc<128,1,0,1><<<dim3(24, 32, 1), 256, 73728>>>(
        hbuf, wq, qkv_b, qkvp, nullptr, nullptr,
        DMODEL, DMODEL, DMODEL, 3 * DMODEL,
        0, 0, 0, 0, 0, 0, 1, 1.f);

    // 3) S[b,h] = (Q K^T) / 8
    gemm_tc<128,1,1,0><<<dim3(8, 8, 64), 256, 73728>>>(
        qkvp, qkvp + DMODEL, nullptr, S, nullptr, nullptr,
        DHEAD, 3 * DMODEL, 3 * DMODEL, NSEQ,
        SQK, DHEAD, SQK, DHEAD, (long long)NHEAD * NN, NN, NHEAD, 0.125f);

    // 4) talking-heads mix -> softmax -> mix
    attn_mix_softmax<<<BSZ * NSEQ, 512, 65536>>>(pl_w, pl_b, pw_w, pw_b, S);

    // 5) O[b,h] = P2 @ V
    gemm_tc<64,0,0,1><<<dim3(1, 8, 64), 256, 55296>>>(
        S, qkvp + 2 * DMODEL, nullptr, obuf, nullptr, nullptr,
        NSEQ, NSEQ, 3 * DMODEL, DMODEL,
        (long long)NHEAD * NN, NN, SQK, DHEAD,
        (long long)NSEQ * DMODEL, DHEAD, NHEAD, 1.f);

    // 6) x1 = x + gamma1 * (obuf @ out_w^T + out_b)
    gemm_tc<128,1,3,0><<<dim3(8, 32, 1), 256, 73728>>>(
        obuf, wo, out_b, out, x, gamma1,
        DMODEL, DMODEL, DMODEL, DMODEL,
        0, 0, 0, 0, 0, 0, 1, 1.f);

    // 7) LN2
    ln_kernel<<<MROWS, 256>>>(out, ln2_w, ln2_b, hbuf);

    // 8) ff = gelu(hbuf @ fc1_w^T + fc1_b)
    gemm_tc<128,1,2,1><<<dim3(32, 32, 1), 256, 73728>>>(
        hbuf, wf1, fc1_b, ff, nullptr, nullptr,
        DMODEL, DMODEL, DMODEL, FFDIM,
        0, 0, 0, 0, 0, 0, 1, 1.f);

    // 9) out = x1 + gamma2 * (ff @ fc2_w^T + fc2_b)
    gemm_tc<128,1,3,0><<<dim3(8, 32, 1), 256, 73728>>>(
        ff, wf2, fc2_b, out, out, gamma2,
        FFDIM, FFDIM, FFDIM, DMODEL,
        0, 0, 0, 0, 0, 0, 1, 1.f);
}

// round 6
// speedup vs baseline: 1.1640x; 1.0441x over previous
#include <cuda_runtime.h>
#include <cuda_bf16.h>
#include <cstdint>

// Problem constants
#define BSZ    4
#define NSEQ   1024
#define DMODEL 1024
#define NHEAD  16
#define DHEAD  64
#define FFDIM  4096
#define MROWS  (BSZ * NSEQ)   // 4096

// ---------------------------------------------------------------------------
// Scratch (device globals; no dynamic allocation allowed)
// ---------------------------------------------------------------------------
__device__ float g_h  [(size_t)MROWS * DMODEL];
__device__ float g_qkv[(size_t)MROWS * 3 * DMODEL];
__device__ __nv_bfloat16 g_S[4ULL * 16 * 1024 * 1024];  // 128 MB scores/probs (bf16)
__device__ float g_o  [(size_t)MROWS * DMODEL];
__device__ float g_ff [(size_t)MROWS * FFDIM];
__device__ float g_wq [3 * DMODEL * DMODEL];            // tf32-rounded weights
__device__ float g_wo [DMODEL * DMODEL];
__device__ float g_wf1[(size_t)FFDIM * DMODEL];
__device__ float g_wf2[(size_t)FFDIM * DMODEL];

// ---------------------------------------------------------------------------
// Helpers
// ---------------------------------------------------------------------------
__device__ __forceinline__ float tf32r(float x) {
    unsigned u;
    asm("cvt.rna.tf32.f32 %0, %1;" : "=r"(u) : "f"(x));
    return __uint_as_float(u);
}

__device__ __forceinline__ void cpa16(void* s, const void* g) {
    unsigned sa = (unsigned)__cvta_generic_to_shared(s);
    asm volatile("cp.async.cg.shared.global [%0], [%1], 16;" :: "r"(sa), "l"(g));
}

__device__ __forceinline__ void mma8(float* c, const unsigned* a, const unsigned* b) {
    asm volatile(
        "mma.sync.aligned.m16n8k8.row.col.f32.tf32.tf32.f32 "
        "{%0,%1,%2,%3}, {%4,%5,%6,%7}, {%8,%9}, {%0,%1,%2,%3};"
        : "+f"(c[0]), "+f"(c[1]), "+f"(c[2]), "+f"(c[3])
        : "r"(a[0]), "r"(a[1]), "r"(a[2]), "r"(a[3]), "r"(b[0]), "r"(b[1]));
}

__device__ __forceinline__ float gelu_tanh(float x) {
    float x3 = x * x * x;
    float u = 0.7978845608028654f * (x + 0.044715f * x3);
    return 0.5f * x * (1.0f + tanhf(u));
}

// ---------------------------------------------------------------------------
// Weight prep: all four weight matrices in ONE launch (grid.y = segment)
// ---------------------------------------------------------------------------
__global__ void round4_k(const float* __restrict__ s0, float* __restrict__ d0, int n0,
                         const float* __restrict__ s1, float* __restrict__ d1, int n1,
                         const float* __restrict__ s2, float* __restrict__ d2, int n2,
                         const float* __restrict__ s3, float* __restrict__ d3, int n3)
{
    int seg = blockIdx.y;
    const float* s = (seg == 0) ? s0 : (seg == 1) ? s1 : (seg == 2) ? s2 : s3;
    float*       d = (seg == 0) ? d0 : (seg == 1) ? d1 : (seg == 2) ? d2 : d3;
    int          n = (seg == 0) ? n0 : (seg == 1) ? n1 : (seg == 2) ? n2 : n3;
    for (int i = blockIdx.x * blockDim.x + threadIdx.x; i < n;
         i += gridDim.x * blockDim.x) {
        float4 v = ((const float4*)s)[i];
        v.x = tf32r(v.x); v.y = tf32r(v.y); v.z = tf32r(v.z); v.w = tf32r(v.w);
        ((float4*)d)[i] = v;
    }
}

// ---------------------------------------------------------------------------
// LayerNorm (output feeds a GEMM A operand -> tf32-round the result)
// ---------------------------------------------------------------------------
__global__ void __launch_bounds__(256) ln_kernel(
    const float* __restrict__ x, const float* __restrict__ w,
    const float* __restrict__ b, float* __restrict__ out)
{
    int row = blockIdx.x;
    int t = threadIdx.x;
    const float4* xr = (const float4*)(x + (size_t)row * DMODEL);
    float4 v = xr[t];
    float s  = v.x + v.y + v.z + v.w;
    float ss = v.x*v.x + v.y*v.y + v.z*v.z + v.w*v.w;
    #pragma unroll
    for (int o = 16; o; o >>= 1) {
        s  += __shfl_xor_sync(0xffffffffu, s,  o);
        ss += __shfl_xor_sync(0xffffffffu, ss, o);
    }
    __shared__ float rs[8], rss[8];
    int wid = t >> 5, ln = t & 31;
    if (ln == 0) { rs[wid] = s; rss[wid] = ss; }
    __syncthreads();
    if (t < 32) {
        s  = (ln < 8) ? rs[ln]  : 0.f;
        ss = (ln < 8) ? rss[ln] : 0.f;
        #pragma unroll
        for (int o = 4; o; o >>= 1) {
            s  += __shfl_xor_sync(0xffffffffu, s,  o);
            ss += __shfl_xor_sync(0xffffffffu, ss, o);
        }
        if (ln == 0) { rs[0] = s; rss[0] = ss; }
    }
    __syncthreads();
    float mean = rs[0] * (1.0f / DMODEL);
    float var  = rss[0] * (1.0f / DMODEL) - mean * mean;
    float inv  = rsqrtf(var + 1e-5f);
    float4 wv = ((const float4*)w)[t];
    float4 bv = ((const float4*)b)[t];
    float4 o4;
    o4.x = tf32r((v.x - mean) * inv * wv.x + bv.x);
    o4.y = tf32r((v.y - mean) * inv * wv.y + bv.y);
    o4.z = tf32r((v.z - mean) * inv * wv.z + bv.z);
    o4.w = tf32r((v.w - mean) * inv * wv.w + bv.w);
    ((float4*)(out + (size_t)row * DMODEL))[t] = o4;
}

// ---------------------------------------------------------------------------
// TF32 tensor-core GEMM (proven config; BK=32 double-buffered).
//   OUTBF=1: C is bf16 (ldc/strides in elements).
// ---------------------------------------------------------------------------
template <int BN, int TRANSB, int EPI, int ROUND, int OUTBF>
__global__ void __launch_bounds__(256, 2) gemm_tc(
    const float* __restrict__ A, const float* __restrict__ Bm,
    const float* __restrict__ bias, float* __restrict__ C,
    const float* __restrict__ res, const float* __restrict__ gamma,
    int K, int lda, int ldb, int ldc,
    long long sAb, long long sAh, long long sBb, long long sBh,
    long long sCb, long long sCh, int Hdim, float scale)
{
    constexpr int BM = 128, BK = 32;
    constexpr int SA  = 36;
    constexpr int SBT = 36;
    constexpr int SBN = BN + 8;
    constexpr int ASTG = BM * SA;
    constexpr int BSTG = TRANSB ? BN * SBT : BK * SBN;
    constexpr int WN = BN / 2;
    constexpr int MI = 2, NI = WN / 8;

    extern __shared__ float smem_g[];
    float* As = smem_g;
    float* Bs = smem_g + 2 * ASTG;

    int bz = blockIdx.z;
    int bb = bz / Hdim, hh = bz - bb * Hdim;
    A  += (size_t)bb * sAb + (size_t)hh * sAh;
    Bm += (size_t)bb * sBb + (size_t)hh * sBh;
    size_t coff = (size_t)bb * sCb + (size_t)hh * sCh;
    float* Cf = C + coff;
    __nv_bfloat16* Cb = ((__nv_bfloat16*)C) + coff;

    int m0 = blockIdx.y * BM;
    int n0 = blockIdx.x * BN;

    int t = threadIdx.x;
    int lane = t & 31, wid = t >> 5;
    int g = lane >> 2, q4 = lane & 3;
    int wm0 = (wid & 3) * 32;
    int wn0 = (wid >> 2) * WN;

    float acc[MI][NI][4];
    #pragma unroll
    for (int mi = 0; mi < MI; mi++)
        #pragma unroll
        for (int ni = 0; ni < NI; ni++)
            #pragma unroll
            for (int rr = 0; rr < 4; rr++) acc[mi][ni][rr] = 0.f;

    const float* Abase = A + (size_t)m0 * lda;
    const float* Bbase = TRANSB ? (Bm + (size_t)n0 * ldb) : (Bm + n0);

    int KT = K / BK;

    auto issue = [&](int stage, int kt) {
        float* Ad = As + stage * ASTG;
        const float* Asrc = Abase + kt * BK;
        #pragma unroll
        for (int i2 = 0; i2 < 4; i2++) {
            int c = i2 * 256 + t;
            int row = c >> 3, ch = (c & 7) << 2;
            cpa16(Ad + row * SA + ch, Asrc + (size_t)row * lda + ch);
        }
        float* Bd = Bs + stage * BSTG;
        if (TRANSB) {
            const float* Bsrc = Bbase + kt * BK;
            #pragma unroll
            for (int i2 = 0; i2 < BN / 32; i2++) {
                int c = i2 * 256 + t;
                int row = c >> 3, ch = (c & 7) << 2;
                cpa16(Bd + row * SBT + ch, Bsrc + (size_t)row * ldb + ch);
            }
        } else {
            const float* Bsrc = Bbase + (size_t)kt * BK * ldb;
            #pragma unroll
            for (int i2 = 0; i2 < (BK * BN) / 1024; i2++) {
                int c = i2 * 256 + t;
                int row = c >> 4, ch = (c & 15) << 2;
                cpa16(Bd + row * SBN + ch, Bsrc + (size_t)row * ldb + ch);
            }
        }
    };

    auto compute = [&](int stage) {
        const float* Asg = As + stage * ASTG;
        const float* Bsg = Bs + stage * BSTG;
        #pragma unroll
        for (int ks = 0; ks < 4; ks++) {
            unsigned a[MI][4];
            #pragma unroll
            for (int mi = 0; mi < MI; mi++) {
                const float* p = Asg + (wm0 + mi * 16 + g) * SA + ks * 8 + q4;
                a[mi][0] = __float_as_uint(p[0]);
                a[mi][1] = __float_as_uint(p[8 * SA]);
                a[mi][2] = __float_as_uint(p[4]);
                a[mi][3] = __float_as_uint(p[8 * SA + 4]);
            }
            unsigned b[NI][2];
            #pragma unroll
            for (int ni = 0; ni < NI; ni++) {
                if (TRANSB) {
                    const float* p = Bsg + (wn0 + ni * 8 + g) * SBT + ks * 8 + q4;
                    b[ni][0] = __float_as_uint(p[0]);
                    b[ni][1] = __float_as_uint(p[4]);
                } else {
                    const float* p = Bsg + (ks * 8 + q4) * SBN + wn0 + ni * 8 + g;
                    b[ni][0] = __float_as_uint(p[0]);
                    b[ni][1] = __float_as_uint(p[4 * SBN]);
                }
            }
            #pragma unroll
            for (int mi = 0; mi < MI; mi++)
                #pragma unroll
                for (int ni = 0; ni < NI; ni++)
                    mma8(acc[mi][ni], a[mi], b[ni]);
        }
    };

    issue(0, 0);
    asm volatile("cp.async.commit_group;");
    for (int kt = 0; kt < KT; kt++) {
        if (kt + 1 < KT) {
            issue((kt + 1) & 1, kt + 1);
            asm volatile("cp.async.commit_group;");
            asm volatile("cp.async.wait_group 1;");
        } else {
            asm volatile("cp.async.wait_group 0;");
        }
        __syncthreads();
        compute(kt & 1);
        __syncthreads();
    }

    #pragma unroll
    for (int mi = 0; mi < MI; mi++) {
        int r0 = m0 + wm0 + mi * 16 + g;
        #pragma unroll
        for (int ni = 0; ni < NI; ni++) {
            int cb = n0 + wn0 + ni * 8 + 2 * q4;
            float bx = 0.f, by = 0.f;
            if ((EPI == 0 || EPI == 2 || EPI == 3) && bias) {
                float2 b2 = *(const float2*)(bias + cb);
                bx = b2.x; by = b2.y;
            }
            float* a4 = acc[mi][ni];
            float v0 = a4[0] + bx, v1 = a4[1] + by;
            float v2 = a4[2] + bx, v3 = a4[3] + by;
            if (EPI == 1) { v0 *= scale; v1 *= scale; v2 *= scale; v3 *= scale; }
            if (EPI == 2) {
                v0 = gelu_tanh(v0); v1 = gelu_tanh(v1);
                v2 = gelu_tanh(v2); v3 = gelu_tanh(v3);
            }
            if (EPI == 3) {
                float2 g2 = *(const float2*)(gamma + cb);
                float2 rA = *(const float2*)(res + (size_t)r0 * ldc + cb);
                float2 rB = *(const float2*)(res + (size_t)(r0 + 8) * ldc + cb);
                v0 = rA.x + g2.x * v0; v1 = rA.y + g2.y * v1;
                v2 = rB.x + g2.x * v2; v3 = rB.y + g2.y * v3;
            }
            if (OUTBF) {
                *(__nv_bfloat162*)(Cb + (size_t)r0 * ldc + cb) =
                    __floats2bfloat162_rn(v0, v1);
                *(__nv_bfloat162*)(Cb + (size_t)(r0 + 8) * ldc + cb) =
                    __floats2bfloat162_rn(v2, v3);
            } else {
                if (ROUND) {
                    v0 = tf32r(v0); v1 = tf32r(v1); v2 = tf32r(v2); v3 = tf32r(v3);
                }
                *(float2*)(Cf + (size_t)r0 * ldc + cb)       = make_float2(v0, v1);
                *(float2*)(Cf + (size_t)(r0 + 8) * ldc + cb) = make_float2(v2, v3);
            }
        }
    }
}

// ---------------------------------------------------------------------------
// P@V GEMM: A = P2 (bf16, [1024 i][1024 j] per (b,h)), B = V (fp32, [j][64d]),
// O fp32 head-interleaved [B][N][H*DH]. tf32 mma; bf16 A fragments rebuilt
// exactly via 16-bit shifts. Batched over z = b*16+h.
// ---------------------------------------------------------------------------
__global__ void __launch_bounds__(256, 2) gemm_pv(
    const __nv_bfloat16* __restrict__ P, const float* __restrict__ Vq,
    float* __restrict__ O)
{
    constexpr int SAB = 40;           // bf16 per A row (80 B)
    constexpr int SBN = 72;           // floats per B row
    constexpr int ASTG = 128 * SAB;   // bf16 units per stage
    constexpr int BSTG = 32 * SBN;    // float units per stage
    const int LDV = 3 * DMODEL;

    extern __shared__ char smp[];
    __nv_bfloat16* As = (__nv_bfloat16*)smp;                 // [2][128][40] bf16
    float* Bs = (float*)(smp + 2 * ASTG * 2);                // [2][32][72]  fp32

    int z = blockIdx.z;
    int bb = z >> 4, hh = z & 15;
    const __nv_bfloat16* Pb = P + (size_t)z * NSEQ * NSEQ;
    const float* Vb = Vq + (size_t)bb * NSEQ * LDV + 2 * DMODEL + hh * DHEAD;
    float* Ob = O + (size_t)bb * NSEQ * DMODEL + hh * DHEAD;

    int m0 = blockIdx.y * 128;
    int t = threadIdx.x, lane = t & 31, wid = t >> 5;
    int g = lane >> 2, q4 = lane & 3;
    int wm0 = (wid & 3) * 32, wn0 = (wid >> 2) * 32;
    int hsel = q4 & 1;

    float acc[2][4][4];
    #pragma unroll
    for (int mi = 0; mi < 2; mi++)
        #pragma unroll
        for (int ni = 0; ni < 4; ni++)
            #pragma unroll
            for (int r = 0; r < 4; r++) acc[mi][ni][r] = 0.f;

    auto issue = [&](int s, int kt) {
        // A: 128 rows x 32 bf16, 4 x 16B chunks per row
        #pragma unroll
        for (int i = 0; i < 2; i++) {
            int c = i * 256 + t;
            int row = c >> 2, ch = c & 3;
            cpa16(As + s * ASTG + row * SAB + ch * 8,
                  Pb + (size_t)(m0 + row) * NSEQ + kt * 32 + ch * 8);
        }
        // B: 32 rows x 64 fp32
        #pragma unroll
        for (int i = 0; i < 2; i++) {
            int c = i * 256 + t;
            int row = c >> 4, col = (c & 15) * 4;
            cpa16(Bs + s * BSTG + row * SBN + col,
                  Vb + (size_t)(kt * 32 + row) * LDV + col);
        }
        asm volatile("cp.async.commit_group;");
    };

    auto compute = [&](int s) {
        const __nv_bfloat16* Ag = As + s * ASTG;
        const float* Bg = Bs + s * BSTG;
        #pragma unroll
        for (int ks = 0; ks < 4; ks++) {
            unsigned a[2][4];
            #pragma unroll
            for (int mi = 0; mi < 2; mi++) {
                int row = wm0 + mi * 16 + g;
                const unsigned* pr  = (const unsigned*)(Ag + row * SAB + ks * 8);
                const unsigned* pr8 = (const unsigned*)(Ag + (row + 8) * SAB + ks * 8);
                unsigned u0 = pr[q4 >> 1],       u1 = pr8[q4 >> 1];
                unsigned u2 = pr[(q4 >> 1) + 2], u3 = pr8[(q4 >> 1) + 2];
                a[mi][0] = hsel ? (u0 & 0xFFFF0000u) : (u0 << 16);
                a[mi][1] = hsel ? (u1 & 0xFFFF0000u) : (u1 << 16);
                a[mi][2] = hsel ? (u2 & 0xFFFF0000u) : (u2 << 16);
                a[mi][3] = hsel ? (u3 & 0xFFFF0000u) : (u3 << 16);
            }
            unsigned b[4][2];
            #pragma unroll
            for (int ni = 0; ni < 4; ni++) {
                const float* p = Bg + (ks * 8 + q4) * SBN + wn0 + ni * 8 + g;
                b[ni][0] = __float_as_uint(p[0]);
                b[ni][1] = __float_as_uint(p[4 * SBN]);
            }
            #pragma unroll
            for (int mi = 0; mi < 2; mi++)
                #pragma unroll
                for (int ni = 0; ni < 4; ni++)
                    mma8(acc[mi][ni], a[mi], b[ni]);
        }
    };

    int KT = NSEQ / 32;
    issue(0, 0);
    for (int kt = 0; kt < KT; kt++) {
        if (kt + 1 < KT) {
            issue((kt + 1) & 1, kt + 1);
            asm volatile("cp.async.wait_group 1;");
        } else {
            asm volatile("cp.async.wait_group 0;");
        }
        __syncthreads();
        compute(kt & 1);
        __syncthreads();
    }

    #pragma unroll
    for (int mi = 0; mi < 2; mi++) {
        int r0 = m0 + wm0 + mi * 16 + g;
        #pragma unroll
        for (int ni = 0; ni < 4; ni++) {
            int cb = wn0 + ni * 8 + 2 * q4;
            float* a4 = acc[mi][ni];
            float v0 = tf32r(a4[0]), v1 = tf32r(a4[1]);
            float v2 = tf32r(a4[2]), v3 = tf32r(a4[3]);
            *(float2*)(Ob + (size_t)r0 * DMODEL + cb)       = make_float2(v0, v1);
            *(float2*)(Ob + (size_t)(r0 + 8) * DMODEL + cb) = make_float2(v2, v3);
        }
    }
}

// ---------------------------------------------------------------------------
// Fused talking-heads: mix -> softmax -> mix, in place on S (bf16 I/O,
// fp32 smem compute). One block per (b, i). 64 KB smem.
// ---------------------------------------------------------------------------
__global__ void __launch_bounds__(512) attn_mix_softmax(
    const float* __restrict__ wl, const float* __restrict__ bl,
    const float* __restrict__ ww, const float* __restrict__ bw,
    __nv_bfloat16* __restrict__ S)
{
    extern __shared__ float Ssh[];      // [16][1024] fp32
    __shared__ float wls[256], wws[256], bls[16], bws[16];

    int t = threadIdx.x;
    int b = blockIdx.x >> 10;
    int i = blockIdx.x & 1023;

    if (t < 256) { wls[t] = wl[t]; wws[t] = ww[t]; }
    if (t < 16)  { bls[t] = bl[t]; bws[t] = bw[t]; }

    __nv_bfloat16* Sg = S + (size_t)(b * NHEAD) * NSEQ * NSEQ + (size_t)i * NSEQ;
    const long long NN = (long long)NSEQ * NSEQ;

    // Load: 16 heads x 1024 bf16 (128 uint4 per head) -> fp32 smem
    #pragma unroll
    for (int ii = 0; ii < 4; ii++) {
        int idx = ii * 512 + t;          // 0..2047
        int h = idx >> 7, j4 = idx & 127;
        uint4 raw = ((const uint4*)(Sg + (size_t)h * NN))[j4];
        float* dst = Ssh + h * NSEQ + j4 * 8;
        unsigned p0 = raw.x, p1 = raw.y, p2 = raw.z, p3 = raw.w;
        dst[0] = __uint_as_float(p0 << 16); dst[1] = __uint_as_float(p0 & 0xFFFF0000u);
        dst[2] = __uint_as_float(p1 << 16); dst[3] = __uint_as_float(p1 & 0xFFFF0000u);
        dst[4] = __uint_as_float(p2 << 16); dst[5] = __uint_as_float(p2 & 0xFFFF0000u);
        dst[6] = __uint_as_float(p3 << 16); dst[7] = __uint_as_float(p3 & 0xFFFF0000u);
    }
    __syncthreads();

    // Pre-softmax mixing (in place: each thread owns its columns)
    #pragma unroll
    for (int jj = 0; jj < 2; jj++) {
        int j = t + jj * 512;
        float sv[16];
        #pragma unroll
        for (int h = 0; h < 16; h++) sv[h] = Ssh[h * NSEQ + j];
        #pragma unroll
        for (int gg = 0; gg < 16; gg++) {
            float acc = bls[gg];
            #pragma unroll
            for (int h = 0; h < 16; h++) acc += wls[gg * 16 + h] * sv[h];
            Ssh[gg * NSEQ + j] = acc;
        }
    }
    __syncthreads();

    // Softmax: one warp per head-row
    {
        int w = t >> 5, l = t & 31;
        float* row = Ssh + w * NSEQ;
        float mx = -1e30f;
        for (int m = l; m < NSEQ; m += 32) mx = fmaxf(mx, row[m]);
        #pragma unroll
        for (int o = 16; o; o >>= 1) mx = fmaxf(mx, __shfl_xor_sync(0xffffffffu, mx, o));
        float sum = 0.f;
        for (int m = l; m < NSEQ; m += 32) {
            float e = __expf(row[m] - mx);
            row[m] = e;
            sum += e;
        }
        #pragma unroll
        for (int o = 16; o; o >>= 1) sum += __shfl_xor_sync(0xffffffffu, sum, o);
        float inv = 1.f / sum;
        for (int m = l; m < NSEQ; m += 32) row[m] *= inv;
    }
    __syncthreads();

    // Post-softmax mixing (in place)
    #pragma unroll
    for (int jj = 0; jj < 2; jj++) {
        int j = t + jj * 512;
        float pv[16];
        #pragma unroll
        for (int h = 0; h < 16; h++) pv[h] = Ssh[h * NSEQ + j];
        #pragma unroll
        for (int gg = 0; gg < 16; gg++) {
            float acc = bws[gg];
            #pragma unroll
            for (int h = 0; h < 16; h++) acc += wws[gg * 16 + h] * pv[h];
            Ssh[gg * NSEQ + j] = acc;
        }
    }
    __syncthreads();

    // Store: fp32 smem -> bf16 global
    #pragma unroll
    for (int ii = 0; ii < 4; ii++) {
        int idx = ii * 512 + t;
        int h = idx >> 7, j4 = idx & 127;
        const float* src = Ssh + h * NSEQ + j4 * 8;
        uint4 raw;
        __nv_bfloat162 h0 = __floats2bfloat162_rn(src[0], src[1]);
        __nv_bfloat162 h1 = __floats2bfloat162_rn(src[2], src[3]);
        __nv_bfloat162 h2 = __floats2bfloat162_rn(src[4], src[5]);
        __nv_bfloat162 h3 = __floats2bfloat162_rn(src[6], src[7]);
        raw.x = *(unsigned*)&h0; raw.y = *(unsigned*)&h1;
        raw.z = *(unsigned*)&h2; raw.w = *(unsigned*)&h3;
        ((uint4*)(Sg + (size_t)h * NN))[j4] = raw;
    }
}

// ---------------------------------------------------------------------------
// Launch
// ---------------------------------------------------------------------------
extern "C" void kernel_launch(void* const* d_in, const int* in_sizes, int n_in,
                              void* d_out, int out_size)
{
    const float* x      = (const float*)d_in[0];
    const float* ln1_w  = (const float*)d_in[1];
    const float* ln1_b  = (const float*)d_in[2];
    const float* qkv_w  = (const float*)d_in[3];
    const float* qkv_b  = (const float*)d_in[4];
    const float* pl_w   = (const float*)d_in[5];
    const float* pl_b   = (const float*)d_in[6];
    const float* pw_w   = (const float*)d_in[7];
    const float* pw_b   = (const float*)d_in[8];
    const float* out_w  = (const float*)d_in[9];
    const float* out_b  = (const float*)d_in[10];
    const float* gamma1 = (const float*)d_in[11];
    const float* ln2_w  = (const float*)d_in[12];
    const float* ln2_b  = (const float*)d_in[13];
    const float* fc1_w  = (const float*)d_in[14];
    const float* fc1_b  = (const float*)d_in[15];
    const float* fc2_w  = (const float*)d_in[16];
    const float* fc2_b  = (const float*)d_in[17];
    const float* gamma2 = (const float*)d_in[18];
    float* out = (float*)d_out;

    float *hbuf, *qkvp, *obuf, *ff, *wq, *wo, *wf1, *wf2;
    __nv_bfloat16* S;
    cudaGetSymbolAddress((void**)&hbuf, g_h);
    cudaGetSymbolAddress((void**)&qkvp, g_qkv);
    cudaGetSymbolAddress((void**)&S,    g_S);
    cudaGetSymbolAddress((void**)&obuf, g_o);
    cudaGetSymbolAddress((void**)&ff,   g_ff);
    cudaGetSymbolAddress((void**)&wq,   g_wq);
    cudaGetSymbolAddress((void**)&wo,   g_wo);
    cudaGetSymbolAddress((void**)&wf1,  g_wf1);
    cudaGetSymbolAddress((void**)&wf2,  g_wf2);

    const int PV_SMEM = 2 * 128 * 40 * 2 + 2 * 32 * 72 * 4;   // 38912 B

    cudaFuncSetAttribute(attn_mix_softmax,
                         cudaFuncAttributeMaxDynamicSharedMemorySize, 65536);
    cudaFuncSetAttribute(gemm_tc<128,1,0,1,0>, cudaFuncAttributeMaxDynamicSharedMemorySize, 73728);
    cudaFuncSetAttribute(gemm_tc<128,1,1,0,1>, cudaFuncAttributeMaxDynamicSharedMemorySize, 73728);
    cudaFuncSetAttribute(gemm_tc<128,1,2,1,0>, cudaFuncAttributeMaxDynamicSharedMemorySize, 73728);
    cudaFuncSetAttribute(gemm_tc<128,1,3,0,0>, cudaFuncAttributeMaxDynamicSharedMemorySize, 73728);
    cudaFuncSetAttribute(gemm_pv, cudaFuncAttributeMaxDynamicSharedMemorySize, PV_SMEM);

    const long long NN  = (long long)NSEQ * NSEQ;
    const long long SQK = (long long)NSEQ * 3 * DMODEL;

    // 0) Round all weights to tf32 (one launch)
    round4_k<<<dim3(1024, 4), 256>>>(
        qkv_w, wq,  3 * DMODEL * DMODEL / 4,
        out_w, wo,  DMODEL * DMODEL / 4,
        fc1_w, wf1, FFDIM * DMODEL / 4,
        fc2_w, wf2, FFDIM * DMODEL / 4);

    // 1) LN1
    ln_kernel<<<MROWS, 256>>>(x, ln1_w, ln1_b, hbuf);

    // 2) qkv = hbuf @ qkv_w^T + qkv_b
    gemm_tc<128,1,0,1,0><<<dim3(24, 32, 1), 256, 73728>>>(
        hbuf, wq, qkv_b, qkvp, nullptr, nullptr,
        DMODEL, DMODEL, DMODEL, 3 * DMODEL,
        0, 0, 0, 0, 0, 0, 1, 1.f);

    // 3) S[b,h] = (Q K^T) / 8   (bf16 output)
    gemm_tc<128,1,1,0,1><<<dim3(8, 8, 64), 256, 73728>>>(
        qkvp, qkvp + DMODEL, nullptr, (float*)S, nullptr, nullptr,
        DHEAD, 3 * DMODEL, 3 * DMODEL, NSEQ,
        SQK, DHEAD, SQK, DHEAD, (long long)NHEAD * NN, NN, NHEAD, 0.125f);

    // 4) talking-heads mix -> softmax -> mix (bf16 in place)
    attn_mix_softmax<<<BSZ * NSEQ, 512, 65536>>>(pl_w, pl_b, pw_w, pw_b, S);

    // 5) O[b,h] = P2 @ V
    gemm_pv<<<dim3(1, 8, 64), 256, PV_SMEM>>>(S, qkvp, obuf);

    // 6) x1 = x + gamma1 * (obuf @ out_w^T + out_b)
    gemm_tc<128,1,3,0,0><<<dim3(8, 32, 1), 256, 73728>>>(
        obuf, wo, out_b, out, x, gamma1,
        DMODEL, DMODEL, DMODEL, DMODEL,
        0, 0, 0, 0, 0, 0, 1, 1.f);

    // 7) LN2
    ln_kernel<<<MROWS, 256>>>(out, ln2_w, ln2_b, hbuf);

    // 8) ff = gelu(hbuf @ fc1_w^T + fc1_b)
    gemm_tc<128,1,2,1,0><<<dim3(32, 32, 1), 256, 73728>>>(
        hbuf, wf1, fc1_b, ff, nullptr, nullptr,
        DMODEL, DMODEL, DMODEL, FFDIM,
        0, 0, 0, 0, 0, 0, 1, 1.f);

    // 9) out = x1 + gamma2 * (ff @ fc2_w^T + fc2_b)
    gemm_tc<128,1,3,0,0><<<dim3(8, 32, 1), 256, 73728>>>(
        ff, wf2, fc2_b, out, out, gamma2,
        FFDIM, FFDIM, FFDIM, DMODEL,
        0, 0, 0, 0, 0, 0, 1, 1.f);
}